// round 4
// baseline (speedup 1.0000x reference)
#include <cuda_runtime.h>
#include <cuda_bf16.h>
#include <cstdint>

#define T_TOK 1024
#define HDIM  2048
#define NEXP  64
#define IDIM  768
#define TOPK  8
#define MAXPOS (T_TOK * TOPK)

#define BM   128
#define BK   32
#define SA   36          // padded row stride (floats); 36*gid mod 32 = 4*gid -> conflict-free
#define N1   64          // gemm1 block N
#define N2   128         // gemm2 block N
#define NSTG 3

#define A_BYTES  (BM * SA * 4)              // 18432
#define B1_BYTES (N1 * SA * 4)              // 9216
#define B2_BYTES (N2 * SA * 4)              // 18432
#define STG1 (A_BYTES + 2 * B1_BYTES)       // 36864
#define STG2 (A_BYTES + B2_BYTES)           // 36864
#define SMEM1 (NSTG * STG1 + 1024)
#define SMEM2 (NSTG * STG2 + 1024)

// ---------------- scratch ----------------
__device__ float d_topk_w[MAXPOS];
__device__ int   d_topk_idx[MAXPOS];
__device__ int   d_counts[NEXP];
__device__ int   d_offsets[NEXP];
__device__ int   d_cursor[NEXP];
__device__ int   d_perm[MAXPOS];
__device__ int   d_posmap[MAXPOS];
__device__ float d_act[(size_t)MAXPOS * IDIM];
__device__ float d_part[(size_t)MAXPOS * HDIM];

// ---------------- PTX helpers ----------------
__device__ __forceinline__ uint32_t f2tf(float f) {
    uint32_t u; asm("cvt.rna.tf32.f32 %0, %1;" : "=r"(u) : "f"(f)); return u;
}
__device__ __forceinline__ void cp16(uint32_t dst, const void* src, int sz) {
    asm volatile("cp.async.cg.shared.global [%0], [%1], 16, %2;\n"
                 :: "r"(dst), "l"(src), "r"(sz));
}
__device__ __forceinline__ void cp_commit() { asm volatile("cp.async.commit_group;\n"); }
template <int N>
__device__ __forceinline__ void cp_wait() { asm volatile("cp.async.wait_group %0;\n" :: "n"(N)); }

__device__ __forceinline__ void mma8(float* d, const uint32_t* a, uint32_t b0, uint32_t b1) {
    asm volatile(
        "mma.sync.aligned.m16n8k8.row.col.f32.tf32.tf32.f32 "
        "{%0,%1,%2,%3},{%4,%5,%6,%7},{%8,%9},{%0,%1,%2,%3};"
        : "+f"(d[0]), "+f"(d[1]), "+f"(d[2]), "+f"(d[3])
        : "r"(a[0]), "r"(a[1]), "r"(a[2]), "r"(a[3]), "r"(b0), "r"(b1));
}

// ---------------- kernel 0: zero counters ----------------
__global__ void zero_counts_kernel() {
    if (threadIdx.x < NEXP) d_counts[threadIdx.x] = 0;
}

// ---------------- kernel 1: router ----------------
__global__ __launch_bounds__(256) void router_kernel(
    const float* __restrict__ x, const float* __restrict__ rw)
{
    __shared__ float xs[HDIM];
    __shared__ float logits[NEXP];
    const int t = blockIdx.x;
    const float* xrow = x + (size_t)t * HDIM;
    for (int j = threadIdx.x; j < HDIM; j += blockDim.x) xs[j] = xrow[j];
    __syncthreads();

    const int warp = threadIdx.x >> 5;
    const int lane = threadIdx.x & 31;
    for (int e = warp; e < NEXP; e += 8) {
        const float* w = rw + (size_t)e * HDIM;
        float s = 0.f;
        for (int j = lane; j < HDIM; j += 32) s = fmaf(xs[j], w[j], s);
        #pragma unroll
        for (int o = 16; o > 0; o >>= 1) s += __shfl_xor_sync(0xffffffffu, s, o);
        if (lane == 0) logits[e] = s;
    }
    __syncthreads();

    if (threadIdx.x == 0) {
        float vals[TOPK]; int idx[TOPK];
        bool used[NEXP];
        #pragma unroll
        for (int e = 0; e < NEXP; e++) used[e] = false;
        for (int k = 0; k < TOPK; k++) {
            float best = -1e30f; int bi = 0;
            for (int e = 0; e < NEXP; e++)
                if (!used[e] && logits[e] > best) { best = logits[e]; bi = e; }
            used[bi] = true; vals[k] = best; idx[k] = bi;
        }
        const float mx = vals[0];
        float sum = 0.f;
        #pragma unroll
        for (int k = 0; k < TOPK; k++) { vals[k] = expf(vals[k] - mx); sum += vals[k]; }
        const float inv = 1.f / sum;
        #pragma unroll
        for (int k = 0; k < TOPK; k++) {
            d_topk_w[t * TOPK + k]   = vals[k] * inv;
            d_topk_idx[t * TOPK + k] = idx[k];
            atomicAdd(&d_counts[idx[k]], 1);
        }
    }
}

// ---------------- kernel 2: exclusive scan ----------------
__global__ void scan_kernel() {
    int off = 0;
    for (int e = 0; e < NEXP; e++) {
        d_offsets[e] = off; d_cursor[e] = off; off += d_counts[e];
    }
}

// ---------------- kernel 3: per-expert token lists ----------------
__global__ void fill_kernel() {
    const int i = blockIdx.x * blockDim.x + threadIdx.x;
    if (i < MAXPOS) {
        const int e = d_topk_idx[i];
        const int pos = atomicAdd(&d_cursor[e], 1);
        d_perm[pos] = i / TOPK;
        d_posmap[i] = pos;
    }
}

// ---------------- kernel 4: fused gate/up tf32 GEMM + SiLU ----------------
// block 128x64 tile, 128 threads (4 warps of 64x32), BK=32, 3-stage cp.async
// grid = (NEXP, IDIM/N1, T_TOK/BM)
__global__ void __launch_bounds__(128, 2) gemm1_kernel(
    const float* __restrict__ x,
    const float* __restrict__ gw,
    const float* __restrict__ uw)
{
    const int e   = blockIdx.x;
    const int cnt = d_counts[e];
    const int m0  = blockIdx.z * BM;
    if (m0 >= cnt) return;
    const int n0  = blockIdx.y * N1;
    const int off = d_offsets[e];

    extern __shared__ float smem[];
    float* sbase = (float*)(((uintptr_t)smem + 1023) & ~(uintptr_t)1023);
    const uint32_t sb = (uint32_t)__cvta_generic_to_shared(sbase);

    const int tid = threadIdx.x;
    // A loader: thread -> one A row (128 rows), 8x16B chunks
    const int ma = m0 + tid;
    const int szA = (ma < cnt) ? 16 : 0;
    const float* aptr = x + (size_t)d_perm[(ma < cnt) ? (off + ma) : off] * HDIM;
    const uint32_t adst = tid * SA * 4;
    // B loader: threads 0-63 gate row, 64-127 up row; 8x16B chunks each
    const int rb  = tid & 63;
    const int mat = tid >> 6;
    const float* bptr = (mat ? uw : gw) + ((size_t)e * IDIM + n0 + rb) * HDIM;
    const uint32_t bdst = A_BYTES + mat * B1_BYTES + rb * SA * 4;

    #define G1_LOAD(st, k0)                                           \
        do {                                                          \
            const uint32_t so = sb + (st) * STG1;                     \
            _Pragma("unroll")                                         \
            for (int i = 0; i < 8; i++) {                             \
                cp16(so + adst + i * 16, aptr + (k0) + i * 4, szA);   \
                cp16(so + bdst + i * 16, bptr + (k0) + i * 4, 16);    \
            }                                                         \
        } while (0)

    G1_LOAD(0, 0);      cp_commit();
    G1_LOAD(1, BK);     cp_commit();
    G1_LOAD(2, 2 * BK); cp_commit();

    const int warp = tid >> 5, lane = tid & 31;
    const int wm = (warp >> 1) * 64, wn = (warp & 1) * 32;
    const int gid = lane >> 2, tig = lane & 3;

    float accg[4][4][4] = {}, accu[4][4][4] = {};

    const int KT = HDIM / BK;   // 64
    for (int kt = 0; kt < KT; kt++) {
        const int buf = kt % NSTG;
        cp_wait<NSTG - 1>();
        __syncthreads();

        const float* A  = sbase + buf * (STG1 / 4);
        const float* Bg = A + (A_BYTES / 4);
        const float* Bu = Bg + (B1_BYTES / 4);

        #pragma unroll
        for (int ks = 0; ks < 4; ks++) {
            const int kk = ks * 8;
            uint32_t af[4][4];
            #pragma unroll
            for (int mt = 0; mt < 4; mt++) {
                const int r = wm + mt * 16 + gid;
                af[mt][0] = f2tf(A[r * SA + kk + tig]);
                af[mt][1] = f2tf(A[(r + 8) * SA + kk + tig]);
                af[mt][2] = f2tf(A[r * SA + kk + tig + 4]);
                af[mt][3] = f2tf(A[(r + 8) * SA + kk + tig + 4]);
            }
            #pragma unroll
            for (int nt = 0; nt < 4; nt++) {
                const int n = wn + nt * 8 + gid;
                const uint32_t bg0 = f2tf(Bg[n * SA + kk + tig]);
                const uint32_t bg1 = f2tf(Bg[n * SA + kk + tig + 4]);
                const uint32_t bu0 = f2tf(Bu[n * SA + kk + tig]);
                const uint32_t bu1 = f2tf(Bu[n * SA + kk + tig + 4]);
                #pragma unroll
                for (int mt = 0; mt < 4; mt++) {
                    mma8(accg[mt][nt], af[mt], bg0, bg1);
                    mma8(accu[mt][nt], af[mt], bu0, bu1);
                }
            }
        }
        __syncthreads();
        if (kt + NSTG < KT) G1_LOAD(buf, (kt + NSTG) * BK);
        cp_commit();
    }

    // epilogue: SiLU(gate)*up, rounded to tf32 bits (gemm2 consumes raw as tf32)
    #pragma unroll
    for (int mt = 0; mt < 4; mt++) {
        const int m_lo = m0 + wm + mt * 16 + gid;
        const int m_hi = m_lo + 8;
        #pragma unroll
        for (int nt = 0; nt < 4; nt++) {
            const int gn = n0 + wn + nt * 8 + tig * 2;
            if (m_lo < cnt) {
                const float g0 = accg[mt][nt][0], g1 = accg[mt][nt][1];
                const float v0 = g0 / (1.f + expf(-g0)) * accu[mt][nt][0];
                const float v1 = g1 / (1.f + expf(-g1)) * accu[mt][nt][1];
                *(float2*)(d_act + (size_t)(off + m_lo) * IDIM + gn) =
                    make_float2(__uint_as_float(f2tf(v0)), __uint_as_float(f2tf(v1)));
            }
            if (m_hi < cnt) {
                const float g2 = accg[mt][nt][2], g3 = accg[mt][nt][3];
                const float v2 = g2 / (1.f + expf(-g2)) * accu[mt][nt][2];
                const float v3 = g3 / (1.f + expf(-g3)) * accu[mt][nt][3];
                *(float2*)(d_act + (size_t)(off + m_hi) * IDIM + gn) =
                    make_float2(__uint_as_float(f2tf(v2)), __uint_as_float(f2tf(v3)));
            }
        }
    }
    #undef G1_LOAD
}

// ---------------- kernel 5: down tf32 GEMM ----------------
// block 128x128 tile, 128 threads (4 warps of 64x64), BK=32, 3-stage cp.async
// grid = (NEXP, HDIM/N2, T_TOK/BM)
__global__ void __launch_bounds__(128, 2) gemm2_kernel(const float* __restrict__ dw)
{
    const int e   = blockIdx.x;
    const int cnt = d_counts[e];
    const int m0  = blockIdx.z * BM;
    if (m0 >= cnt) return;
    const int n0  = blockIdx.y * N2;
    const int off = d_offsets[e];

    extern __shared__ float smem[];
    float* sbase = (float*)(((uintptr_t)smem + 1023) & ~(uintptr_t)1023);
    const uint32_t sb = (uint32_t)__cvta_generic_to_shared(sbase);

    const int tid = threadIdx.x;
    const int ma = m0 + tid;
    const int szA = (ma < cnt) ? 16 : 0;
    const float* aptr = d_act + (size_t)((ma < cnt) ? (off + ma) : off) * IDIM;
    const uint32_t adst = tid * SA * 4;
    const float* bptr = dw + ((size_t)e * HDIM + n0 + tid) * IDIM;
    const uint32_t bdst = A_BYTES + tid * SA * 4;

    #define G2_LOAD(st, k0)                                           \
        do {                                                          \
            const uint32_t so = sb + (st) * STG2;                     \
            _Pragma("unroll")                                         \
            for (int i = 0; i < 8; i++) {                             \
                cp16(so + adst + i * 16, aptr + (k0) + i * 4, szA);   \
                cp16(so + bdst + i * 16, bptr + (k0) + i * 4, 16);    \
            }                                                         \
        } while (0)

    G2_LOAD(0, 0);      cp_commit();
    G2_LOAD(1, BK);     cp_commit();
    G2_LOAD(2, 2 * BK); cp_commit();

    const int warp = tid >> 5, lane = tid & 31;
    const int wm = (warp >> 1) * 64, wn = (warp & 1) * 64;
    const int gid = lane >> 2, tig = lane & 3;

    float acc[4][8][4] = {};

    const int KT = IDIM / BK;   // 24
    for (int kt = 0; kt < KT; kt++) {
        const int buf = kt % NSTG;
        cp_wait<NSTG - 1>();
        __syncthreads();

        const float* A = sbase + buf * (STG2 / 4);
        const float* B = A + (A_BYTES / 4);

        #pragma unroll
        for (int ks = 0; ks < 4; ks++) {
            const int kk = ks * 8;
            uint32_t af[4][4];
            #pragma unroll
            for (int mt = 0; mt < 4; mt++) {
                const int r = wm + mt * 16 + gid;
                // d_act rows are pre-rounded tf32 bit patterns: no cvt needed
                af[mt][0] = __float_as_uint(A[r * SA + kk + tig]);
                af[mt][1] = __float_as_uint(A[(r + 8) * SA + kk + tig]);
                af[mt][2] = __float_as_uint(A[r * SA + kk + tig + 4]);
                af[mt][3] = __float_as_uint(A[(r + 8) * SA + kk + tig + 4]);
            }
            #pragma unroll
            for (int nt = 0; nt < 8; nt++) {
                const int n = wn + nt * 8 + gid;
                const uint32_t b0 = f2tf(B[n * SA + kk + tig]);
                const uint32_t b1 = f2tf(B[n * SA + kk + tig + 4]);
                #pragma unroll
                for (int mt = 0; mt < 4; mt++)
                    mma8(acc[mt][nt], af[mt], b0, b1);
            }
        }
        __syncthreads();
        if (kt + NSTG < KT) G2_LOAD(buf, (kt + NSTG) * BK);
        cp_commit();
    }

    #pragma unroll
    for (int mt = 0; mt < 4; mt++) {
        const int m_lo = m0 + wm + mt * 16 + gid;
        const int m_hi = m_lo + 8;
        #pragma unroll
        for (int nt = 0; nt < 8; nt++) {
            const int gn = n0 + wn + nt * 8 + tig * 2;
            if (m_lo < cnt)
                *(float2*)(d_part + (size_t)(off + m_lo) * HDIM + gn) =
                    make_float2(acc[mt][nt][0], acc[mt][nt][1]);
            if (m_hi < cnt)
                *(float2*)(d_part + (size_t)(off + m_hi) * HDIM + gn) =
                    make_float2(acc[mt][nt][2], acc[mt][nt][3]);
        }
    }
    #undef G2_LOAD
}

// ---------------- kernel 6: deterministic combine ----------------
__global__ __launch_bounds__(256) void combine_kernel(float* __restrict__ out)
{
    const int t = blockIdx.x;
    const int h = blockIdx.y * 256 + threadIdx.x;
    float w[TOPK]; int pos[TOPK];
    #pragma unroll
    for (int k = 0; k < TOPK; k++) {
        w[k]   = d_topk_w[t * TOPK + k];
        pos[k] = d_posmap[t * TOPK + k];
    }
    float s = 0.f;
    #pragma unroll
    for (int k = 0; k < TOPK; k++)
        s = fmaf(w[k], d_part[(size_t)pos[k] * HDIM + h], s);
    out[(size_t)t * HDIM + h] = s;
}

// ---------------- launch ----------------
extern "C" void kernel_launch(void* const* d_in, const int* in_sizes, int n_in,
                              void* d_out, int out_size)
{
    const float* x  = (const float*)d_in[0];
    const float* rw = (const float*)d_in[1];
    const float* gw = (const float*)d_in[2];
    const float* uw = (const float*)d_in[3];
    const float* dw = (const float*)d_in[4];
    float* out = (float*)d_out;

    cudaFuncSetAttribute(gemm1_kernel, cudaFuncAttributeMaxDynamicSharedMemorySize, SMEM1);
    cudaFuncSetAttribute(gemm2_kernel, cudaFuncAttributeMaxDynamicSharedMemorySize, SMEM2);

    zero_counts_kernel<<<1, 64>>>();
    router_kernel<<<T_TOK, 256>>>(x, rw);
    scan_kernel<<<1, 1>>>();
    fill_kernel<<<MAXPOS / 256, 256>>>();
    gemm1_kernel<<<dim3(NEXP, IDIM / N1, T_TOK / BM), 128, SMEM1>>>(x, gw, uw);
    gemm2_kernel<<<dim3(NEXP, HDIM / N2, T_TOK / BM), 128, SMEM2>>>(dw);
    combine_kernel<<<dim3(T_TOK, HDIM / 256), 256>>>(out);
}